// round 16
// baseline (speedup 1.0000x reference)
#include <cuda_runtime.h>
#include <cuda_bf16.h>
#include <cstdint>
#include <math.h>

// Problem dims (fixed)
#define BB    8
#define HH    64
#define WWID  64
#define CC    512
#define CFG   64
#define CHDIM 256
#define HW    4096
#define HWD   1024
#define MROWS 32768          // BB*HW
#define NPROJ 384            // CFG + CFG + CHDIM

typedef __nv_bfloat16 bf16;
typedef __nv_bfloat162 bf162;

// -------------------- device scratch (BSS, allocation-free) ----------------
__device__ bf16  d_thetabf[(size_t)MROWS * CFG];      // theta, compact [m][64]
__device__ bf16  d_phibf[(size_t)BB * HWD * CFG];
__device__ bf16  d_gbf  [(size_t)BB * HWD * CHDIM];   // pooled g, scaled by 1/Z
__device__ bf16  d_ebf  [(size_t)BB * HWD * HW];      // e = exp(s), unnormalized
__device__ float d_part [(size_t)BB * HWD * 4];       // per-(row, jgroup) partials
__device__ bf16  d_obf  [(size_t)MROWS * CHDIM];      // attention out

// -------------------- PTX helpers -----------------------------------------
__device__ __forceinline__ unsigned smem_u32(const void* p) {
    return (unsigned)__cvta_generic_to_shared(p);
}
__device__ __forceinline__ void ldsm_x4(unsigned a[4], unsigned addr) {
    asm volatile("ldmatrix.sync.aligned.m8n8.x4.shared.b16 {%0,%1,%2,%3}, [%4];"
        : "=r"(a[0]), "=r"(a[1]), "=r"(a[2]), "=r"(a[3]) : "r"(addr));
}
__device__ __forceinline__ void ldsm_x4_t(unsigned a[4], unsigned addr) {
    asm volatile("ldmatrix.sync.aligned.m8n8.x4.trans.shared.b16 {%0,%1,%2,%3}, [%4];"
        : "=r"(a[0]), "=r"(a[1]), "=r"(a[2]), "=r"(a[3]) : "r"(addr));
}
__device__ __forceinline__ void ldsm_x2(unsigned b[2], unsigned addr) {
    asm volatile("ldmatrix.sync.aligned.m8n8.x2.shared.b16 {%0,%1}, [%2];"
        : "=r"(b[0]), "=r"(b[1]) : "r"(addr));
}
__device__ __forceinline__ void ldsm_x2_t(unsigned b[2], unsigned addr) {
    asm volatile("ldmatrix.sync.aligned.m8n8.x2.trans.shared.b16 {%0,%1}, [%2];"
        : "=r"(b[0]), "=r"(b[1]) : "r"(addr));
}
__device__ __forceinline__ void mma16816(float c[4], const unsigned a[4], const unsigned b[2]) {
    asm volatile(
        "mma.sync.aligned.m16n8k16.row.col.f32.bf16.bf16.f32 "
        "{%0,%1,%2,%3}, {%4,%5,%6,%7}, {%8,%9}, {%0,%1,%2,%3};"
        : "+f"(c[0]), "+f"(c[1]), "+f"(c[2]), "+f"(c[3])
        : "r"(a[0]), "r"(a[1]), "r"(a[2]), "r"(a[3]), "r"(b[0]), "r"(b[1]));
}
__device__ __forceinline__ uint4 cvt8(const float* p) {
    float4 f0 = *(const float4*)p;
    float4 f1 = *(const float4*)(p + 4);
    bf162 h0 = __float22bfloat162_rn(make_float2(f0.x, f0.y));
    bf162 h1 = __float22bfloat162_rn(make_float2(f0.z, f0.w));
    bf162 h2 = __float22bfloat162_rn(make_float2(f1.x, f1.y));
    bf162 h3 = __float22bfloat162_rn(make_float2(f1.z, f1.w));
    uint4 v;
    v.x = *(unsigned*)&h0; v.y = *(unsigned*)&h1;
    v.z = *(unsigned*)&h2; v.w = *(unsigned*)&h3;
    return v;
}

// -------------------- epilogue functors ------------------------------------
struct EpiO {     // bf16 attention out
    __device__ void operator()(int b, int r, int c, float v0, float v1) const {
        bf162 p; p.x = __float2bfloat16(v0); p.y = __float2bfloat16(v1);
        *(bf162*)&d_obf[((size_t)b * HW + r) * CHDIM + c] = p;
    }
};
struct EpiFinal { // out = gamma*(acc+bias) + x, fp32
    const float* x; const float* ob; const float* gm; float* out;
    __device__ void operator()(int, int r, int c, float v0, float v1) const {
        float g = gm[0];
        size_t off = (size_t)r * CC + c;
        float2 xv = *(const float2*)&x[off];
        float2 o;
        o.x = g * (v0 + ob[c])     + xv.x;
        o.y = g * (v1 + ob[c + 1]) + xv.y;
        *(float2*)&out[off] = o;
    }
};

// -------------------- bf16 GEMM: 2-stage smem, 1 sync per chunk ------------
// (round-10 proven core; BF32: B fp32 in gmem ([k][n] layout), cvt at staging)
template<bool AKM, bool BNK, bool AF32, bool BF32, class Epi>
__global__ __launch_bounds__(256, 2) void gemm_bf16(
    const void* __restrict__ Av, const void* __restrict__ Bv,
    int lda, int ldb, int K, size_t bsA, size_t bsB, Epi epi)
{
    constexpr int AST = AKM ? 136 : 40;
    constexpr int ASZ = AKM ? 32 * 136 : 128 * 40;
    constexpr int BST = BNK ? 40 : 136;
    constexpr int BSZ = BNK ? 128 * 40 : 32 * 136;
    __shared__ __align__(16) bf16 As[2 * ASZ];
    __shared__ __align__(16) bf16 Bs[2 * BSZ];

    const bf16*  A   = (const bf16*)Av;
    const float* A32 = (const float*)Av;
    const bf16*  B   = (const bf16*)Bv;
    const float* B32 = (const float*)Bv;
    const int bz = blockIdx.z;
    A   += (size_t)bz * bsA;
    A32 += (size_t)bz * bsA;
    B   += (size_t)bz * bsB;
    B32 += (size_t)bz * bsB;
    const int m0 = blockIdx.y * 128, n0 = blockIdx.x * 128;

    const int t = threadIdx.x;
    const unsigned lane = t & 31;
    const int w = t >> 5;
    const int wm0 = (w >> 2) * 64;
    const int wn0 = (w & 3) * 32;

    uint4 ra[2], rb[2];
    auto ldA = [&](int k0) {
        #pragma unroll
        for (int it = 0; it < 2; it++) {
            int e = it * 256 + t;
            if (AF32) {
                int r = e >> 2, c = (e & 3) << 3;
                ra[it] = cvt8(A32 + (size_t)(m0 + r) * lda + k0 + c);
            } else if (!AKM) {
                int r = e >> 2, c = (e & 3) << 3;
                ra[it] = *(const uint4*)(A + (size_t)(m0 + r) * lda + k0 + c);
            } else {
                int r = e >> 4, c = (e & 15) << 3;
                ra[it] = *(const uint4*)(A + (size_t)(k0 + r) * lda + m0 + c);
            }
        }
    };
    auto ldB = [&](int k0) {
        #pragma unroll
        for (int it = 0; it < 2; it++) {
            int e = it * 256 + t;
            if (BNK) { int r = e >> 2, c = (e & 3) << 3;
                rb[it] = *(const uint4*)(B + (size_t)(n0 + r) * ldb + k0 + c); }
            else if (BF32) {
                int r = e >> 4, c = (e & 15) << 3;
                rb[it] = cvt8(B32 + (size_t)(k0 + r) * ldb + n0 + c);
            } else {
                int r = e >> 4, c = (e & 15) << 3;
                rb[it] = *(const uint4*)(B + (size_t)(k0 + r) * ldb + n0 + c);
            }
        }
    };
    auto stAB = [&](int s) {
        bf16* Ap = As + s * ASZ;
        bf16* Bp = Bs + s * BSZ;
        #pragma unroll
        for (int it = 0; it < 2; it++) {
            int e = it * 256 + t;
            if (!AKM) { int r = e >> 2, c = (e & 3) << 3; *(uint4*)&Ap[r * 40 + c] = ra[it]; }
            else      { int r = e >> 4, c = (e & 15) << 3; *(uint4*)&Ap[r * 136 + c] = ra[it]; }
            if (BNK)  { int r = e >> 2, c = (e & 3) << 3; *(uint4*)&Bp[r * 40 + c] = rb[it]; }
            else      { int r = e >> 4, c = (e & 15) << 3; *(uint4*)&Bp[r * 136 + c] = rb[it]; }
        }
    };

    float cc[4][4][4] = {};
    const unsigned asb0 = smem_u32(As), bsb0 = smem_u32(Bs);
    const int nch = K / 32;

    ldA(0); ldB(0); stAB(0);

    for (int ch = 0; ch < nch; ch++) {
        __syncthreads();
        const bool more = (ch + 1 < nch);
        if (more) { ldA((ch + 1) * 32); ldB((ch + 1) * 32); }
        const unsigned asb = asb0 + (unsigned)((ch & 1) * ASZ * 2);
        const unsigned bsb = bsb0 + (unsigned)((ch & 1) * BSZ * 2);

        #pragma unroll
        for (int ks = 0; ks < 2; ks++) {
            const int kk = ks * 16;
            unsigned afr[4][4];
            #pragma unroll
            for (int mi = 0; mi < 4; mi++) {
                unsigned addr;
                if (!AKM) {
                    addr = asb + (unsigned)(((wm0 + mi * 16 + (lane & 15)) * AST
                                  + kk + ((lane >> 4) << 3)) * 2);
                    ldsm_x4(afr[mi], addr);
                } else {
                    addr = asb + (unsigned)(((kk + (lane & 7) + ((lane >> 4) << 3)) * AST
                                  + wm0 + mi * 16 + (((lane >> 3) & 1) << 3)) * 2);
                    ldsm_x4_t(afr[mi], addr);
                }
            }
            unsigned bfr[4][2];
            #pragma unroll
            for (int ni = 0; ni < 4; ni++) {
                unsigned addr;
                if (!BNK) {
                    addr = bsb + (unsigned)(((kk + (lane & 15)) * BST + wn0 + ni * 8) * 2);
                    ldsm_x2_t(bfr[ni], addr);
                } else {
                    addr = bsb + (unsigned)(((wn0 + ni * 8 + (lane & 7)) * BST
                                  + kk + (((lane >> 3) & 1) << 3)) * 2);
                    ldsm_x2(bfr[ni], addr);
                }
            }
            #pragma unroll
            for (int mi = 0; mi < 4; mi++)
                #pragma unroll
                for (int ni = 0; ni < 4; ni++)
                    mma16816(cc[mi][ni], afr[mi], bfr[ni]);
        }

        if (more) stAB((ch + 1) & 1);
    }

    #pragma unroll
    for (int mi = 0; mi < 4; mi++)
        #pragma unroll
        for (int ni = 0; ni < 4; ni++) {
            int r  = m0 + wm0 + mi * 16 + (int)(lane >> 2);
            int ci = n0 + wn0 + ni * 8 + (int)((lane & 3) << 1);
            epi(bz, r,     ci, cc[mi][ni][0], cc[mi][ni][1]);
            epi(bz, r + 8, ci, cc[mi][ni][2], cc[mi][ni][3]);
        }
}

// -------------------- proj GEMM: fp32 in, fused bias + maxpool -------------
// B (weights) read fp32 directly from tw/pw/gw; bias from tb/pb/gb.
// nb=0: cols 0-63 theta (tw), 64-127 phi (pw).  nb=1/2: g halves (gw).
__global__ __launch_bounds__(256, 2) void k_proj(
    const float* __restrict__ X,
    const float* __restrict__ tw, const float* __restrict__ pw,
    const float* __restrict__ gw,
    const float* __restrict__ tb, const float* __restrict__ pb,
    const float* __restrict__ gb)
{
    constexpr int ASZ = 128 * 40;
    constexpr int BSZ = 32 * 136;
    __shared__ __align__(16) bf16 smbuf[2 * ASZ + 2 * BSZ];   // >= 128*136
    bf16* As = smbuf;
    bf16* Bs = smbuf + 2 * ASZ;

    const int nb = blockIdx.x;             // 0..2
    const int m0 = blockIdx.y * 128;

    const int t = threadIdx.x;
    const unsigned lane = t & 31;
    const int w = t >> 5;
    const int wm0 = (w >> 2) * 64;
    const int wn0 = (w & 3) * 32;

    uint4 ra[2], rb[2];
    auto ldA = [&](int k0) {
        #pragma unroll
        for (int it = 0; it < 2; it++) {
            int e = it * 256 + t;
            int r = e >> 2, c = (e & 3) << 3;
            ra[it] = cvt8(X + (size_t)(m0 + r) * CC + k0 + c);
        }
    };
    auto ldB = [&](int k0) {
        #pragma unroll
        for (int it = 0; it < 2; it++) {
            int e = it * 256 + t;
            int r = e >> 4, c = (e & 15) << 3;   // c 8-aligned: one source region
            const float* src; int off, ldw;
            if (nb == 0) {
                if (c < 64) { src = tw; off = c;      ldw = 64; }
                else        { src = pw; off = c - 64; ldw = 64; }
            } else          { src = gw; off = (nb - 1) * 128 + c; ldw = 256; }
            rb[it] = cvt8(src + (size_t)(k0 + r) * ldw + off);
        }
    };
    auto stAB = [&](int s) {
        bf16* Ap = As + s * ASZ;
        bf16* Bp = Bs + s * BSZ;
        #pragma unroll
        for (int it = 0; it < 2; it++) {
            int e = it * 256 + t;
            { int r = e >> 2, c = (e & 3) << 3; *(uint4*)&Ap[r * 40 + c] = ra[it]; }
            { int r = e >> 4, c = (e & 15) << 3; *(uint4*)&Bp[r * 136 + c] = rb[it]; }
        }
    };

    float cc[4][4][4] = {};
    const unsigned asb0 = smem_u32(As), bsb0 = smem_u32(Bs);

    ldA(0); ldB(0); stAB(0);

    for (int ch = 0; ch < 16; ch++) {                  // K=512
        __syncthreads();
        const bool more = (ch + 1 < 16);
        if (more) { ldA((ch + 1) * 32); ldB((ch + 1) * 32); }
        const unsigned asb = asb0 + (unsigned)((ch & 1) * ASZ * 2);
        const unsigned bsb = bsb0 + (unsigned)((ch & 1) * BSZ * 2);

        #pragma unroll
        for (int ks = 0; ks < 2; ks++) {
            const int kk = ks * 16;
            unsigned afr[4][4];
            #pragma unroll
            for (int mi = 0; mi < 4; mi++)
                ldsm_x4(afr[mi], asb + (unsigned)(((wm0 + mi * 16 + (lane & 15)) * 40
                                     + kk + ((lane >> 4) << 3)) * 2));
            unsigned bfr[4][2];
            #pragma unroll
            for (int ni = 0; ni < 4; ni++)
                ldsm_x2_t(bfr[ni], bsb + (unsigned)(((kk + (lane & 15)) * 136
                                       + wn0 + ni * 8) * 2));
            #pragma unroll
            for (int mi = 0; mi < 4; mi++)
                #pragma unroll
                for (int ni = 0; ni < 4; ni++)
                    mma16816(cc[mi][ni], afr[mi], bfr[ni]);
        }

        if (more) stAB((ch + 1) & 1);
    }

    // ---- stage biased bf16 tile into smem [128][136] ----
    __syncthreads();
    #pragma unroll
    for (int mi = 0; mi < 4; mi++)
        #pragma unroll
        for (int ni = 0; ni < 4; ni++) {
            int rl = wm0 + mi * 16 + (int)(lane >> 2);
            int ci = wn0 + ni * 8 + (int)((lane & 3) << 1);
            float b0, b1;
            if (nb == 0) {
                if (ci < 64) { b0 = tb[ci];      b1 = tb[ci + 1]; }
                else         { b0 = pb[ci - 64]; b1 = pb[ci - 63]; }
            } else {
                int gc = (nb - 1) * 128 + ci;
                b0 = gb[gc]; b1 = gb[gc + 1];
            }
            bf162 p;
            p.x = __float2bfloat16(cc[mi][ni][0] + b0);
            p.y = __float2bfloat16(cc[mi][ni][1] + b1);
            *(bf162*)&smbuf[rl * 136 + ci] = p;
            bf162 q;
            q.x = __float2bfloat16(cc[mi][ni][2] + b0);
            q.y = __float2bfloat16(cc[mi][ni][3] + b1);
            *(bf162*)&smbuf[(rl + 8) * 136 + ci] = q;
        }
    __syncthreads();

    const int b     = m0 >> 12;                        // batch
    const int ibase = ((m0 & 4095) >> 7) << 5;         // pooled row base
    auto pool2v = [&](int wp, int col) -> bf162 {
        bf162 a0 = *(const bf162*)&smbuf[(2 * wp) * 136 + col];
        bf162 a1 = *(const bf162*)&smbuf[(2 * wp + 1) * 136 + col];
        bf162 a2 = *(const bf162*)&smbuf[(64 + 2 * wp) * 136 + col];
        bf162 a3 = *(const bf162*)&smbuf[(65 + 2 * wp) * 136 + col];
        bf162 o;
        o.x = __float2bfloat16(fmaxf(fmaxf(__bfloat162float(a0.x), __bfloat162float(a1.x)),
                                     fmaxf(__bfloat162float(a2.x), __bfloat162float(a3.x))));
        o.y = __float2bfloat16(fmaxf(fmaxf(__bfloat162float(a0.y), __bfloat162float(a1.y)),
                                     fmaxf(__bfloat162float(a2.y), __bfloat162float(a3.y))));
        return o;
    };

    if (nb == 0) {
        {
            const int r = t >> 1, half = t & 1;
            const unsigned* sp = (const unsigned*)&smbuf[r * 136 + half * 32];
            unsigned* gp = (unsigned*)&d_thetabf[(size_t)(m0 + r) * CFG + half * 32];
            #pragma unroll
            for (int k = 0; k < 16; k++) gp[k] = sp[k];
        }
        #pragma unroll
        for (int k = 0; k < 4; k++) {
            int o = k * 256 + t;
            int wp = o >> 5, c2 = (o & 31) << 1;
            *(bf162*)&d_phibf[((size_t)b * HWD + ibase + wp) * CFG + c2]
                = pool2v(wp, 64 + c2);
        }
    } else {
        #pragma unroll
        for (int k = 0; k < 8; k++) {
            int o = k * 256 + t;
            int wp = o >> 6, c2 = (o & 63) << 1;
            *(bf162*)&d_gbf[((size_t)b * HWD + ibase + wp) * CHDIM + (nb - 1) * 128 + c2]
                = pool2v(wp, c2);
        }
    }
}

// -------------------- dedicated e-GEMM: phi reuse over 8 j-tiles -----------
// (round-13 proven, verbatim)
__global__ __launch_bounds__(256, 2) void k_egemm()
{
    constexpr int CSZ = 128 * 40;
    __shared__ __align__(16) bf16 As[2 * CSZ];
    __shared__ __align__(16) bf16 Bs[2][2 * CSZ];
    __shared__ float rs[128][4];

    const int jg = blockIdx.x;
    const int i0 = blockIdx.y * 128;
    const int bz = blockIdx.z;
    const bf16* Aph = d_phibf   + (size_t)bz * HWD * CFG;
    const bf16* Bth = d_thetabf + (size_t)bz * HW * CFG;
    bf16* eb = d_ebf + ((size_t)bz * HWD + i0) * HW;

    const int t = threadIdx.x;
    const unsigned lane = t & 31;
    const int w = t >> 5;
    const int wm0 = (w >> 2) * 64;
    const int wn0 = (w & 3) * 32;
    const unsigned asb = smem_u32(As);

    #pragma unroll
    for (int ch = 0; ch < 2; ch++)
        #pragma unroll
        for (int it = 0; it < 2; it++) {
            int e = it * 256 + t;
            int r = e >> 2, c = (e & 3) << 3;
            *(uint4*)&As[ch * CSZ + r * 40 + c] =
                *(const uint4*)(Aph + (size_t)(i0 + r) * CFG + ch * 32 + c);
        }

    uint4 rB[4];
    auto ldB = [&](int jt) {
        const int j0 = jg * 1024 + jt * 128;
        #pragma unroll
        for (int ch = 0; ch < 2; ch++)
            #pragma unroll
            for (int it = 0; it < 2; it++) {
                int e = it * 256 + t;
                int r = e >> 2, c = (e & 3) << 3;
                rB[ch * 2 + it] =
                    *(const uint4*)(Bth + (size_t)(j0 + r) * CFG + ch * 32 + c);
            }
    };
    auto stB = [&](int s) {
        #pragma unroll
        for (int ch = 0; ch < 2; ch++)
            #pragma unroll
            for (int it = 0; it < 2; it++) {
                int e = it * 256 + t;
                int r = e >> 2, c = (e & 3) << 3;
                *(uint4*)&Bs[s][ch * CSZ + r * 40 + c] = rB[ch * 2 + it];
            }
    };

    float zp[4][2];
    #pragma unroll
    for (int mi = 0; mi < 4; mi++) { zp[mi][0] = 0.f; zp[mi][1] = 0.f; }

    ldB(0); stB(0);

    for (int jt = 0; jt < 8; jt++) {
        __syncthreads();
        const bool more = (jt + 1 < 8);
        if (more) ldB(jt + 1);

        const unsigned bsb = smem_u32(Bs[jt & 1]);
        float cc[4][4][4] = {};
        #pragma unroll
        for (int ch = 0; ch < 2; ch++) {
            const unsigned asc = asb + (unsigned)(ch * CSZ * 2);
            const unsigned bsc = bsb + (unsigned)(ch * CSZ * 2);
            #pragma unroll
            for (int ks = 0; ks < 2; ks++) {
                const int kk = ks * 16;
                unsigned afr[4][4];
                #pragma unroll
                for (int mi = 0; mi < 4; mi++)
                    ldsm_x4(afr[mi], asc + (unsigned)(((wm0 + mi * 16 + (lane & 15)) * 40
                                         + kk + ((lane >> 4) << 3)) * 2));
                unsigned bfr[4][2];
                #pragma unroll
                for (int ni = 0; ni < 4; ni++)
                    ldsm_x2(bfr[ni], bsc + (unsigned)(((wn0 + ni * 8 + (lane & 7)) * 40
                                         + kk + (((lane >> 3) & 1) << 3)) * 2));
                #pragma unroll
                for (int mi = 0; mi < 4; mi++)
                    #pragma unroll
                    for (int ni = 0; ni < 4; ni++)
                        mma16816(cc[mi][ni], afr[mi], bfr[ni]);
            }
        }

        const int jbase = jg * 1024 + jt * 128;
        #pragma unroll
        for (int mi = 0; mi < 4; mi++) {
            const int rl = wm0 + mi * 16 + (int)(lane >> 2);
            #pragma unroll
            for (int ni = 0; ni < 4; ni++) {
                const int cj = jbase + wn0 + ni * 8 + (int)((lane & 3) << 1);
                float e0 = __expf(cc[mi][ni][0]), e1 = __expf(cc[mi][ni][1]);
                float e2 = __expf(cc[mi][ni][2]), e3 = __expf(cc[mi][ni][3]);
                bf162 p; p.x = __float2bfloat16(e0); p.y = __float2bfloat16(e1);
                *(bf162*)&eb[(size_t)rl * HW + cj] = p;
                bf162 q; q.x = __float2bfloat16(e2); q.y = __float2bfloat16(e3);
                *(bf162*)&eb[(size_t)(rl + 8) * HW + cj] = q;
                zp[mi][0] += e0 + e1;
                zp[mi][1] += e2 + e3;
            }
        }

        if (more) stB((jt + 1) & 1);
    }

    #pragma unroll
    for (int mi = 0; mi < 4; mi++) {
        float rp0 = zp[mi][0], rp1 = zp[mi][1];
        rp0 += __shfl_xor_sync(0xffffffffu, rp0, 1);
        rp0 += __shfl_xor_sync(0xffffffffu, rp0, 2);
        rp1 += __shfl_xor_sync(0xffffffffu, rp1, 1);
        rp1 += __shfl_xor_sync(0xffffffffu, rp1, 2);
        if ((lane & 3) == 0) {
            int rl = wm0 + mi * 16 + (int)(lane >> 2);
            rs[rl][w & 3]     = rp0;
            rs[rl + 8][w & 3] = rp1;
        }
    }
    __syncthreads();
    if (t < 128) {
        float z = (rs[t][0] + rs[t][1]) + (rs[t][2] + rs[t][3]);
        d_part[((size_t)bz * HWD + i0 + t) * 4 + jg] = z;
    }
}

// -------------------- fused Z reduce + g scaling (vectorized 8x) ------------
__global__ __launch_bounds__(256) void k_zgscale() {
    int idx = blockIdx.x * 256 + threadIdx.x;     // uint4 groups: 8*1024*32
    if (idx >= BB * HWD * 32) return;
    int row = idx >> 5;                           // (b*1024 + i)
    float4 pp = *(const float4*)&d_part[(size_t)row * 4];
    float iz = 1.0f / ((pp.x + pp.y) + (pp.z + pp.w));
    uint4 v = *(uint4*)&d_gbf[(size_t)idx * 8];
    bf162* h = (bf162*)&v;
    #pragma unroll
    for (int k = 0; k < 4; k++) {
        h[k].x = __float2bfloat16(__bfloat162float(h[k].x) * iz);
        h[k].y = __float2bfloat16(__bfloat162float(h[k].y) * iz);
    }
    *(uint4*)&d_gbf[(size_t)idx * 8] = v;
}

// -------------------- launch -----------------------------------------------
extern "C" void kernel_launch(void* const* d_in, const int* in_sizes, int n_in,
                              void* d_out, int out_size)
{
    const float* x  = (const float*)d_in[0];
    const float* tw = (const float*)d_in[1];
    const float* tb = (const float*)d_in[2];
    const float* pw = (const float*)d_in[3];
    const float* pb = (const float*)d_in[4];
    const float* gw = (const float*)d_in[5];
    const float* gb = (const float*)d_in[6];
    const float* ow = (const float*)d_in[7];
    const float* ob = (const float*)d_in[8];
    const float* gm = (const float*)d_in[9];
    float* out = (float*)d_out;

    void *p_gbf, *p_ebf, *p_obf;
    cudaGetSymbolAddress(&p_gbf, d_gbf);
    cudaGetSymbolAddress(&p_ebf, d_ebf);
    cudaGetSymbolAddress(&p_obf, d_obf);

    // 1) projections (fp32 weights on the fly) + bias + fused 2x2 maxpool
    k_proj<<<dim3(3, MROWS / 128), 256>>>(x, tw, pw, gw, tb, pb, gb);

    // 2) e = exp(phi @ theta^T): phi reuse over 8 j-tiles per block
    k_egemm<<<dim3(HW / 1024, HWD / 128, BB), 256>>>();

    // 3) fused Z reduction + 1/Z fold into g rows
    k_zgscale<<<(BB * HWD * 32 + 255) / 256, 256>>>();

    // 4) o = e^T @ g' per batch: [4096,1024] @ [1024,256], A is [k][m]
    gemm_bf16<true, false, false, false, EpiO><<<dim3(CHDIM / 128, HW / 128, BB), 256>>>(
        p_ebf, p_gbf, HW, CHDIM, HWD,
        (size_t)HWD * HW, (size_t)HWD * CHDIM, EpiO{});

    // 5) out = gamma*(o @ ow(fp32) + ob) + x: [32768,256] @ [256,512]
    EpiFinal ef{x, ob, gm, out};
    gemm_bf16<false, false, false, true, EpiFinal><<<dim3(CC / 128, MROWS / 128, 1), 256>>>(
        p_obf, ow, CHDIM, CC, CHDIM, 0, 0, ef);
}

// round 17
// speedup vs baseline: 1.0725x; 1.0725x over previous
#include <cuda_runtime.h>
#include <cuda_bf16.h>
#include <cstdint>
#include <math.h>

// Problem dims (fixed)
#define BB    8
#define HH    64
#define WWID  64
#define CC    512
#define CFG   64
#define CHDIM 256
#define HW    4096
#define HWD   1024
#define MROWS 32768          // BB*HW
#define NPROJ 384            // CFG + CFG + CHDIM

typedef __nv_bfloat16 bf16;
typedef __nv_bfloat162 bf162;

// -------------------- device scratch (BSS, allocation-free) ----------------
__device__ bf16  d_wcat [(size_t)CC * NPROJ];         // [theta|phi|g] weights
__device__ bf16  d_owbf [(size_t)CHDIM * CC];         // o3 weights
__device__ float d_bcat [NPROJ];                      // [theta|phi|g] biases
__device__ bf16  d_thetabf[(size_t)MROWS * CFG];      // theta, compact [m][64]
__device__ bf16  d_phibf[(size_t)BB * HWD * CFG];
__device__ bf16  d_gbf  [(size_t)BB * HWD * CHDIM];   // pooled g, scaled by 1/Z
__device__ bf16  d_ebf  [(size_t)BB * HWD * HW];      // e = exp(s), unnormalized
__device__ float d_part [(size_t)BB * HWD * 4];       // per-(row, jgroup) partials
__device__ bf16  d_obf  [(size_t)MROWS * CHDIM];      // attention out

// -------------------- PTX helpers -----------------------------------------
__device__ __forceinline__ unsigned smem_u32(const void* p) {
    return (unsigned)__cvta_generic_to_shared(p);
}
__device__ __forceinline__ void ldsm_x4(unsigned a[4], unsigned addr) {
    asm volatile("ldmatrix.sync.aligned.m8n8.x4.shared.b16 {%0,%1,%2,%3}, [%4];"
        : "=r"(a[0]), "=r"(a[1]), "=r"(a[2]), "=r"(a[3]) : "r"(addr));
}
__device__ __forceinline__ void ldsm_x4_t(unsigned a[4], unsigned addr) {
    asm volatile("ldmatrix.sync.aligned.m8n8.x4.trans.shared.b16 {%0,%1,%2,%3}, [%4];"
        : "=r"(a[0]), "=r"(a[1]), "=r"(a[2]), "=r"(a[3]) : "r"(addr));
}
__device__ __forceinline__ void ldsm_x2(unsigned b[2], unsigned addr) {
    asm volatile("ldmatrix.sync.aligned.m8n8.x2.shared.b16 {%0,%1}, [%2];"
        : "=r"(b[0]), "=r"(b[1]) : "r"(addr));
}
__device__ __forceinline__ void ldsm_x2_t(unsigned b[2], unsigned addr) {
    asm volatile("ldmatrix.sync.aligned.m8n8.x2.trans.shared.b16 {%0,%1}, [%2];"
        : "=r"(b[0]), "=r"(b[1]) : "r"(addr));
}
__device__ __forceinline__ void mma16816(float c[4], const unsigned a[4], const unsigned b[2]) {
    asm volatile(
        "mma.sync.aligned.m16n8k16.row.col.f32.bf16.bf16.f32 "
        "{%0,%1,%2,%3}, {%4,%5,%6,%7}, {%8,%9}, {%0,%1,%2,%3};"
        : "+f"(c[0]), "+f"(c[1]), "+f"(c[2]), "+f"(c[3])
        : "r"(a[0]), "r"(a[1]), "r"(a[2]), "r"(a[3]), "r"(b[0]), "r"(b[1]));
}

// -------------------- epilogue functors ------------------------------------
struct EpiO {     // bf16 attention out
    __device__ void operator()(int b, int r, int c, float v0, float v1) const {
        bf162 p; p.x = __float2bfloat16(v0); p.y = __float2bfloat16(v1);
        *(bf162*)&d_obf[((size_t)b * HW + r) * CHDIM + c] = p;
    }
};
struct EpiFinal { // out = gamma*(acc+bias) + x, fp32
    const float* x; const float* ob; const float* gm; float* out;
    __device__ void operator()(int, int r, int c, float v0, float v1) const {
        float g = gm[0];
        size_t off = (size_t)r * CC + c;
        float2 xv = *(const float2*)&x[off];
        float2 o;
        o.x = g * (v0 + ob[c])     + xv.x;
        o.y = g * (v1 + ob[c + 1]) + xv.y;
        *(float2*)&out[off] = o;
    }
};

// -------------------- bf16 GEMM: 2-stage smem, 1 sync per chunk ------------
// (round-10 proven, verbatim)
template<bool AKM, bool BNK, bool AF32, class Epi>
__global__ __launch_bounds__(256, 2) void gemm_bf16(
    const void* __restrict__ Av, const bf16* __restrict__ B,
    int lda, int ldb, int K, size_t bsA, size_t bsB, Epi epi)
{
    constexpr int AST = AKM ? 136 : 40;
    constexpr int ASZ = AKM ? 32 * 136 : 128 * 40;
    constexpr int BST = BNK ? 40 : 136;
    constexpr int BSZ = BNK ? 128 * 40 : 32 * 136;
    __shared__ __align__(16) bf16 As[2 * ASZ];
    __shared__ __align__(16) bf16 Bs[2 * BSZ];

    const bf16*  A   = (const bf16*)Av;
    const float* A32 = (const float*)Av;
    const int bz = blockIdx.z;
    A   += (size_t)bz * bsA;
    A32 += (size_t)bz * bsA;
    B   += (size_t)bz * bsB;
    const int m0 = blockIdx.y * 128, n0 = blockIdx.x * 128;

    const int t = threadIdx.x;
    const unsigned lane = t & 31;
    const int w = t >> 5;
    const int wm0 = (w >> 2) * 64;
    const int wn0 = (w & 3) * 32;

    uint4 ra[2], rb[2];
    auto ldA = [&](int k0) {
        #pragma unroll
        for (int it = 0; it < 2; it++) {
            int e = it * 256 + t;
            if (AF32) {
                int r = e >> 2, c = (e & 3) << 3;
                const float* p = A32 + (size_t)(m0 + r) * lda + k0 + c;
                float4 f0 = *(const float4*)p;
                float4 f1 = *(const float4*)(p + 4);
                bf162 h0 = __float22bfloat162_rn(make_float2(f0.x, f0.y));
                bf162 h1 = __float22bfloat162_rn(make_float2(f0.z, f0.w));
                bf162 h2 = __float22bfloat162_rn(make_float2(f1.x, f1.y));
                bf162 h3 = __float22bfloat162_rn(make_float2(f1.z, f1.w));
                ra[it].x = *(unsigned*)&h0; ra[it].y = *(unsigned*)&h1;
                ra[it].z = *(unsigned*)&h2; ra[it].w = *(unsigned*)&h3;
            } else if (!AKM) {
                int r = e >> 2, c = (e & 3) << 3;
                ra[it] = *(const uint4*)(A + (size_t)(m0 + r) * lda + k0 + c);
            } else {
                int r = e >> 4, c = (e & 15) << 3;
                ra[it] = *(const uint4*)(A + (size_t)(k0 + r) * lda + m0 + c);
            }
        }
    };
    auto ldB = [&](int k0) {
        #pragma unroll
        for (int it = 0; it < 2; it++) {
            int e = it * 256 + t;
            if (BNK) { int r = e >> 2, c = (e & 3) << 3;
                rb[it] = *(const uint4*)(B + (size_t)(n0 + r) * ldb + k0 + c); }
            else     { int r = e >> 4, c = (e & 15) << 3;
                rb[it] = *(const uint4*)(B + (size_t)(k0 + r) * ldb + n0 + c); }
        }
    };
    auto stAB = [&](int s) {
        bf16* Ap = As + s * ASZ;
        bf16* Bp = Bs + s * BSZ;
        #pragma unroll
        for (int it = 0; it < 2; it++) {
            int e = it * 256 + t;
            if (!AKM) { int r = e >> 2, c = (e & 3) << 3; *(uint4*)&Ap[r * 40 + c] = ra[it]; }
            else      { int r = e >> 4, c = (e & 15) << 3; *(uint4*)&Ap[r * 136 + c] = ra[it]; }
            if (BNK)  { int r = e >> 2, c = (e & 3) << 3; *(uint4*)&Bp[r * 40 + c] = rb[it]; }
            else      { int r = e >> 4, c = (e & 15) << 3; *(uint4*)&Bp[r * 136 + c] = rb[it]; }
        }
    };

    float cc[4][4][4] = {};
    const unsigned asb0 = smem_u32(As), bsb0 = smem_u32(Bs);
    const int nch = K / 32;

    ldA(0); ldB(0); stAB(0);

    for (int ch = 0; ch < nch; ch++) {
        __syncthreads();
        const bool more = (ch + 1 < nch);
        if (more) { ldA((ch + 1) * 32); ldB((ch + 1) * 32); }
        const unsigned asb = asb0 + (unsigned)((ch & 1) * ASZ * 2);
        const unsigned bsb = bsb0 + (unsigned)((ch & 1) * BSZ * 2);

        #pragma unroll
        for (int ks = 0; ks < 2; ks++) {
            const int kk = ks * 16;
            unsigned afr[4][4];
            #pragma unroll
            for (int mi = 0; mi < 4; mi++) {
                unsigned addr;
                if (!AKM) {
                    addr = asb + (unsigned)(((wm0 + mi * 16 + (lane & 15)) * AST
                                  + kk + ((lane >> 4) << 3)) * 2);
                    ldsm_x4(afr[mi], addr);
                } else {
                    addr = asb + (unsigned)(((kk + (lane & 7) + ((lane >> 4) << 3)) * AST
                                  + wm0 + mi * 16 + (((lane >> 3) & 1) << 3)) * 2);
                    ldsm_x4_t(afr[mi], addr);
                }
            }
            unsigned bfr[4][2];
            #pragma unroll
            for (int ni = 0; ni < 4; ni++) {
                unsigned addr;
                if (!BNK) {
                    addr = bsb + (unsigned)(((kk + (lane & 15)) * BST + wn0 + ni * 8) * 2);
                    ldsm_x2_t(bfr[ni], addr);
                } else {
                    addr = bsb + (unsigned)(((wn0 + ni * 8 + (lane & 7)) * BST
                                  + kk + (((lane >> 3) & 1) << 3)) * 2);
                    ldsm_x2(bfr[ni], addr);
                }
            }
            #pragma unroll
            for (int mi = 0; mi < 4; mi++)
                #pragma unroll
                for (int ni = 0; ni < 4; ni++)
                    mma16816(cc[mi][ni], afr[mi], bfr[ni]);
        }

        if (more) stAB((ch + 1) & 1);
    }

    #pragma unroll
    for (int mi = 0; mi < 4; mi++)
        #pragma unroll
        for (int ni = 0; ni < 4; ni++) {
            int r  = m0 + wm0 + mi * 16 + (int)(lane >> 2);
            int ci = n0 + wn0 + ni * 8 + (int)((lane & 3) << 1);
            epi(bz, r,     ci, cc[mi][ni][0], cc[mi][ni][1]);
            epi(bz, r + 8, ci, cc[mi][ni][2], cc[mi][ni][3]);
        }
}

// -------------------- proj GEMM with fused bias + maxpool ------------------
__global__ __launch_bounds__(256, 2) void k_proj(const float* __restrict__ X,
                                                 const bf16* __restrict__ Bw)
{
    constexpr int ASZ = 128 * 40;
    constexpr int BSZ = 32 * 136;
    __shared__ __align__(16) bf16 smbuf[2 * ASZ + 2 * BSZ];   // >= 128*136
    bf16* As = smbuf;
    bf16* Bs = smbuf + 2 * ASZ;

    const int nb = blockIdx.x;             // 0..2
    const int m0 = blockIdx.y * 128;
    const int n0 = nb * 128;

    const int t = threadIdx.x;
    const unsigned lane = t & 31;
    const int w = t >> 5;
    const int wm0 = (w >> 2) * 64;
    const int wn0 = (w & 3) * 32;

    uint4 ra[2], rb[2];
    auto ldA = [&](int k0) {
        #pragma unroll
        for (int it = 0; it < 2; it++) {
            int e = it * 256 + t;
            int r = e >> 2, c = (e & 3) << 3;
            const float* p = X + (size_t)(m0 + r) * CC + k0 + c;
            float4 f0 = *(const float4*)p;
            float4 f1 = *(const float4*)(p + 4);
            bf162 h0 = __float22bfloat162_rn(make_float2(f0.x, f0.y));
            bf162 h1 = __float22bfloat162_rn(make_float2(f0.z, f0.w));
            bf162 h2 = __float22bfloat162_rn(make_float2(f1.x, f1.y));
            bf162 h3 = __float22bfloat162_rn(make_float2(f1.z, f1.w));
            ra[it].x = *(unsigned*)&h0; ra[it].y = *(unsigned*)&h1;
            ra[it].z = *(unsigned*)&h2; ra[it].w = *(unsigned*)&h3;
        }
    };
    auto ldB = [&](int k0) {
        #pragma unroll
        for (int it = 0; it < 2; it++) {
            int e = it * 256 + t;
            int r = e >> 4, c = (e & 15) << 3;
            rb[it] = *(const uint4*)(Bw + (size_t)(k0 + r) * NPROJ + n0 + c);
        }
    };
    auto stAB = [&](int s) {
        bf16* Ap = As + s * ASZ;
        bf16* Bp = Bs + s * BSZ;
        #pragma unroll
        for (int it = 0; it < 2; it++) {
            int e = it * 256 + t;
            { int r = e >> 2, c = (e & 3) << 3; *(uint4*)&Ap[r * 40 + c] = ra[it]; }
            { int r = e >> 4, c = (e & 15) << 3; *(uint4*)&Bp[r * 136 + c] = rb[it]; }
        }
    };

    float cc[4][4][4] = {};
    const unsigned asb0 = smem_u32(As), bsb0 = smem_u32(Bs);

    ldA(0); ldB(0); stAB(0);

    for (int ch = 0; ch < 16; ch++) {                  // K=512
        __syncthreads();
        const bool more = (ch + 1 < 16);
        if (more) { ldA((ch + 1) * 32); ldB((ch + 1) * 32); }
        const unsigned asb = asb0 + (unsigned)((ch & 1) * ASZ * 2);
        const unsigned bsb = bsb0 + (unsigned)((ch & 1) * BSZ * 2);

        #pragma unroll
        for (int ks = 0; ks < 2; ks++) {
            const int kk = ks * 16;
            unsigned afr[4][4];
            #pragma unroll
            for (int mi = 0; mi < 4; mi++)
                ldsm_x4(afr[mi], asb + (unsigned)(((wm0 + mi * 16 + (lane & 15)) * 40
                                     + kk + ((lane >> 4) << 3)) * 2));
            unsigned bfr[4][2];
            #pragma unroll
            for (int ni = 0; ni < 4; ni++)
                ldsm_x2_t(bfr[ni], bsb + (unsigned)(((kk + (lane & 15)) * 136
                                       + wn0 + ni * 8) * 2));
            #pragma unroll
            for (int mi = 0; mi < 4; mi++)
                #pragma unroll
                for (int ni = 0; ni < 4; ni++)
                    mma16816(cc[mi][ni], afr[mi], bfr[ni]);
        }

        if (more) stAB((ch + 1) & 1);
    }

    // ---- stage biased bf16 tile into smem [128][136] ----
    __syncthreads();
    #pragma unroll
    for (int mi = 0; mi < 4; mi++)
        #pragma unroll
        for (int ni = 0; ni < 4; ni++) {
            int rl = wm0 + mi * 16 + (int)(lane >> 2);
            int ci = wn0 + ni * 8 + (int)((lane & 3) << 1);
            float b0 = d_bcat[n0 + ci], b1 = d_bcat[n0 + ci + 1];
            bf162 p;
            p.x = __float2bfloat16(cc[mi][ni][0] + b0);
            p.y = __float2bfloat16(cc[mi][ni][1] + b1);
            *(bf162*)&smbuf[rl * 136 + ci] = p;
            bf162 q;
            q.x = __float2bfloat16(cc[mi][ni][2] + b0);
            q.y = __float2bfloat16(cc[mi][ni][3] + b1);
            *(bf162*)&smbuf[(rl + 8) * 136 + ci] = q;
        }
    __syncthreads();

    const int b     = m0 >> 12;                        // batch
    const int ibase = ((m0 & 4095) >> 7) << 5;         // pooled row base
    auto pool2v = [&](int wp, int col) -> bf162 {
        bf162 a0 = *(const bf162*)&smbuf[(2 * wp) * 136 + col];
        bf162 a1 = *(const bf162*)&smbuf[(2 * wp + 1) * 136 + col];
        bf162 a2 = *(const bf162*)&smbuf[(64 + 2 * wp) * 136 + col];
        bf162 a3 = *(const bf162*)&smbuf[(65 + 2 * wp) * 136 + col];
        bf162 o;
        o.x = __float2bfloat16(fmaxf(fmaxf(__bfloat162float(a0.x), __bfloat162float(a1.x)),
                                     fmaxf(__bfloat162float(a2.x), __bfloat162float(a3.x))));
        o.y = __float2bfloat16(fmaxf(fmaxf(__bfloat162float(a0.y), __bfloat162float(a1.y)),
                                     fmaxf(__bfloat162float(a2.y), __bfloat162float(a3.y))));
        return o;
    };

    if (nb == 0) {
        {
            const int r = t >> 1, half = t & 1;
            const unsigned* sp = (const unsigned*)&smbuf[r * 136 + half * 32];
            unsigned* gp = (unsigned*)&d_thetabf[(size_t)(m0 + r) * CFG + half * 32];
            #pragma unroll
            for (int k = 0; k < 16; k++) gp[k] = sp[k];
        }
        #pragma unroll
        for (int k = 0; k < 4; k++) {
            int o = k * 256 + t;
            int wp = o >> 5, c2 = (o & 31) << 1;
            *(bf162*)&d_phibf[((size_t)b * HWD + ibase + wp) * CFG + c2]
                = pool2v(wp, 64 + c2);
        }
    } else {
        #pragma unroll
        for (int k = 0; k < 8; k++) {
            int o = k * 256 + t;
            int wp = o >> 6, c2 = (o & 63) << 1;
            *(bf162*)&d_gbf[((size_t)b * HWD + ibase + wp) * CHDIM + (nb - 1) * 128 + c2]
                = pool2v(wp, c2);
        }
    }
}

// -------------------- dedicated e-GEMM: phi reuse over 8 j-tiles -----------
__global__ __launch_bounds__(256, 2) void k_egemm()
{
    constexpr int CSZ = 128 * 40;
    __shared__ __align__(16) bf16 As[2 * CSZ];
    __shared__ __align__(16) bf16 Bs[2][2 * CSZ];
    __shared__ float rs[128][4];

    const int jg = blockIdx.x;
    const int i0 = blockIdx.y * 128;
    const int bz = blockIdx.z;
    const bf16* Aph = d_phibf   + (size_t)bz * HWD * CFG;
    const bf16* Bth = d_thetabf + (size_t)bz * HW * CFG;
    bf16* eb = d_ebf + ((size_t)bz * HWD + i0) * HW;

    const int t = threadIdx.x;
    const unsigned lane = t & 31;
    const int w = t >> 5;
    const int wm0 = (w >> 2) * 64;
    const int wn0 = (w & 3) * 32;
    const unsigned asb = smem_u32(As);

    #pragma unroll
    for (int ch = 0; ch < 2; ch++)
        #pragma unroll
        for (int it = 0; it < 2; it++) {
            int e = it * 256 + t;
            int r = e >> 2, c = (e & 3) << 3;
            *(uint4*)&As[ch * CSZ + r * 40 + c] =
                *(const uint4*)(Aph + (size_t)(i0 + r) * CFG + ch * 32 + c);
        }

    uint4 rB[4];
    auto ldB = [&](int jt) {
        const int j0 = jg * 1024 + jt * 128;
        #pragma unroll
        for (int ch = 0; ch < 2; ch++)
            #pragma unroll
            for (int it = 0; it < 2; it++) {
                int e = it * 256 + t;
                int r = e >> 2, c = (e & 3) << 3;
                rB[ch * 2 + it] =
                    *(const uint4*)(Bth + (size_t)(j0 + r) * CFG + ch * 32 + c);
            }
    };
    auto stB = [&](int s) {
        #pragma unroll
        for (int ch = 0; ch < 2; ch++)
            #pragma unroll
            for (int it = 0; it < 2; it++) {
                int e = it * 256 + t;
                int r = e >> 2, c = (e & 3) << 3;
                *(uint4*)&Bs[s][ch * CSZ + r * 40 + c] = rB[ch * 2 + it];
            }
    };

    float zp[4][2];
    #pragma unroll
    for (int mi = 0; mi < 4; mi++) { zp[mi][0] = 0.f; zp[mi][1] = 0.f; }

    ldB(0); stB(0);

    for (int jt = 0; jt < 8; jt++) {
        __syncthreads();
        const bool more = (jt + 1 < 8);
        if (more) ldB(jt + 1);

        const unsigned bsb = smem_u32(Bs[jt & 1]);
        float cc[4][4][4] = {};
        #pragma unroll
        for (int ch = 0; ch < 2; ch++) {
            const unsigned asc = asb + (unsigned)(ch * CSZ * 2);
            const unsigned bsc = bsb + (unsigned)(ch * CSZ * 2);
            #pragma unroll
            for (int ks = 0; ks < 2; ks++) {
                const int kk = ks * 16;
                unsigned afr[4][4];
                #pragma unroll
                for (int mi = 0; mi < 4; mi++)
                    ldsm_x4(afr[mi], asc + (unsigned)(((wm0 + mi * 16 + (lane & 15)) * 40
                                         + kk + ((lane >> 4) << 3)) * 2));
                unsigned bfr[4][2];
                #pragma unroll
                for (int ni = 0; ni < 4; ni++)
                    ldsm_x2(bfr[ni], bsc + (unsigned)(((wn0 + ni * 8 + (lane & 7)) * 40
                                         + kk + (((lane >> 3) & 1) << 3)) * 2));
                #pragma unroll
                for (int mi = 0; mi < 4; mi++)
                    #pragma unroll
                    for (int ni = 0; ni < 4; ni++)
                        mma16816(cc[mi][ni], afr[mi], bfr[ni]);
            }
        }

        const int jbase = jg * 1024 + jt * 128;
        #pragma unroll
        for (int mi = 0; mi < 4; mi++) {
            const int rl = wm0 + mi * 16 + (int)(lane >> 2);
            #pragma unroll
            for (int ni = 0; ni < 4; ni++) {
                const int cj = jbase + wn0 + ni * 8 + (int)((lane & 3) << 1);
                float e0 = __expf(cc[mi][ni][0]), e1 = __expf(cc[mi][ni][1]);
                float e2 = __expf(cc[mi][ni][2]), e3 = __expf(cc[mi][ni][3]);
                bf162 p; p.x = __float2bfloat16(e0); p.y = __float2bfloat16(e1);
                *(bf162*)&eb[(size_t)rl * HW + cj] = p;
                bf162 q; q.x = __float2bfloat16(e2); q.y = __float2bfloat16(e3);
                *(bf162*)&eb[(size_t)(rl + 8) * HW + cj] = q;
                zp[mi][0] += e0 + e1;
                zp[mi][1] += e2 + e3;
            }
        }

        if (more) stB((jt + 1) & 1);
    }

    #pragma unroll
    for (int mi = 0; mi < 4; mi++) {
        float rp0 = zp[mi][0], rp1 = zp[mi][1];
        rp0 += __shfl_xor_sync(0xffffffffu, rp0, 1);
        rp0 += __shfl_xor_sync(0xffffffffu, rp0, 2);
        rp1 += __shfl_xor_sync(0xffffffffu, rp1, 1);
        rp1 += __shfl_xor_sync(0xffffffffu, rp1, 2);
        if ((lane & 3) == 0) {
            int rl = wm0 + mi * 16 + (int)(lane >> 2);
            rs[rl][w & 3]     = rp0;
            rs[rl + 8][w & 3] = rp1;
        }
    }
    __syncthreads();
    if (t < 128) {
        float z = (rs[t][0] + rs[t][1]) + (rs[t][2] + rs[t][3]);
        d_part[((size_t)bz * HWD + i0 + t) * 4 + jg] = z;
    }
}

// -------------------- prep: weights/biases to bf16 --------------------------
__global__ __launch_bounds__(256) void k_cvt_w(
    const float* __restrict__ tw, const float* __restrict__ pw, const float* __restrict__ gw,
    const float* __restrict__ tb, const float* __restrict__ pb, const float* __restrict__ gb,
    const float* __restrict__ ow)
{
    int i = blockIdx.x * 256 + threadIdx.x;
    const int W1 = CC * NPROJ, W2 = W1 + CHDIM * CC;
    if (i < W1) {
        int r = i / NPROJ, c = i % NPROJ;
        float v = (c < 64) ? tw[r * 64 + c] : (c < 128) ? pw[r * 64 + c - 64]
                                            : gw[r * 256 + c - 128];
        d_wcat[i] = __float2bfloat16(v);
    } else if (i < W2) {
        int j = i - W1;
        d_owbf[j] = __float2bfloat16(ow[j]);
    } else if (i < W2 + NPROJ) {
        int c = i - W2;
        d_bcat[c] = (c < 64) ? tb[c] : (c < 128) ? pb[c - 64] : gb[c - 128];
    }
}

// -------------------- fused Z reduce + g scaling (vectorized 8x) ------------
__global__ __launch_bounds__(256) void k_zgscale() {
    int idx = blockIdx.x * 256 + threadIdx.x;     // uint4 groups: 8*1024*32
    if (idx >= BB * HWD * 32) return;
    int row = idx >> 5;                           // (b*1024 + i)
    const float* p = &d_part[(size_t)row * 4];
    float iz = 1.0f / ((p[0] + p[1]) + (p[2] + p[3]));
    uint4 v = *(uint4*)&d_gbf[(size_t)idx * 8];
    bf162* h = (bf162*)&v;
    #pragma unroll
    for (int k = 0; k < 4; k++) {
        h[k].x = __float2bfloat16(__bfloat162float(h[k].x) * iz);
        h[k].y = __float2bfloat16(__bfloat162float(h[k].y) * iz);
    }
    *(uint4*)&d_gbf[(size_t)idx * 8] = v;
}

// -------------------- launch -----------------------------------------------
extern "C" void kernel_launch(void* const* d_in, const int* in_sizes, int n_in,
                              void* d_out, int out_size)
{
    const float* x  = (const float*)d_in[0];
    const float* tw = (const float*)d_in[1];
    const float* tb = (const float*)d_in[2];
    const float* pw = (const float*)d_in[3];
    const float* pb = (const float*)d_in[4];
    const float* gw = (const float*)d_in[5];
    const float* gb = (const float*)d_in[6];
    const float* ow = (const float*)d_in[7];
    const float* ob = (const float*)d_in[8];
    const float* gm = (const float*)d_in[9];
    float* out = (float*)d_out;

    void *p_wcat, *p_owbf, *p_gbf, *p_ebf, *p_obf;
    cudaGetSymbolAddress(&p_wcat, d_wcat);
    cudaGetSymbolAddress(&p_owbf, d_owbf);
    cudaGetSymbolAddress(&p_gbf,  d_gbf);
    cudaGetSymbolAddress(&p_ebf,  d_ebf);
    cudaGetSymbolAddress(&p_obf,  d_obf);

    // 0) weights to bf16 (x converted on the fly inside proj GEMM)
    k_cvt_w<<<(CC * NPROJ + CHDIM * CC + NPROJ + 255) / 256, 256>>>(tw, pw, gw, tb, pb, gb, ow);

    // 1) projections + bias + fused 2x2 maxpool -> theta (compact), phi, g
    k_proj<<<dim3(3, MROWS / 128), 256>>>(x, (const bf16*)p_wcat);

    // 2) e = exp(phi @ theta^T): phi reuse over 8 j-tiles per block
    k_egemm<<<dim3(HW / 1024, HWD / 128, BB), 256>>>();

    // 3) fused Z reduction + 1/Z fold into g rows (vectorized)
    k_zgscale<<<(BB * HWD * 32 + 255) / 256, 256>>>();

    // 4) o = e^T @ g' per batch: [4096,1024] @ [1024,256], A is [k][m]
    gemm_bf16<true, false, false, EpiO><<<dim3(CHDIM / 128, HW / 128, BB), 256>>>(
        p_ebf, (const bf16*)p_gbf, HW, CHDIM, HWD,
        (size_t)HWD * HW, (size_t)HWD * CHDIM, EpiO{});

    // 5) out = gamma*(o @ o3_w + b) + x: [32768,256] @ [256,512]
    EpiFinal ef{x, ob, gm, out};
    gemm_bf16<false, false, false, EpiFinal><<<dim3(CC / 128, MROWS / 128, 1), 256>>>(
        p_obf, (const bf16*)p_owbf, CHDIM, CC, CHDIM, 0, 0, ef);
}